// round 1
// baseline (speedup 1.0000x reference)
#include <cuda_runtime.h>
#include <math.h>

#define Bn 4
#define Tn 2048
#define En 1024
#define Hn 2048
// 1/sqrt(2048)
#define ATTN_SCALE 0.022097086912079612f

// Scratch (static device allocation — no cudaMalloc allowed)
__device__ float g_q[Bn * Tn * Hn];                 // 64 MiB
__device__ float g_v[Bn * Tn * Hn];                 // 64 MiB
__device__ float g_e[Bn * Tn * Tn];                 // 64 MiB
__device__ float g_d[Bn * Tn];                      // inverse column sums

// ----------------------------------------------------------------------------
// 128x128 tile, K-step 8, 256 threads, 8x8 per-thread microtile (split 4+4).
// TRANSB=false: Bm is [K,N] row-major.  TRANSB=true: Bm is [N,K] row-major.
// MODE 0: C = acc + bias[col]          (projection)
// MODE 1: C = (r>=c) ? exp(acc*scale) : 1.0   (scores -> exp'd masked scores)
// MODE 2: C = acc                      (output GEMM)
// ----------------------------------------------------------------------------
template <bool TRANSB, int MODE>
__global__ __launch_bounds__(256) void gemm128(
    const float* __restrict__ A, const float* __restrict__ Bm,
    const float* __restrict__ bias, float* __restrict__ C,
    int M, int N, int K, size_t sA, size_t sB, size_t sC)
{
    A  += (size_t)blockIdx.z * sA;
    Bm += (size_t)blockIdx.z * sB;
    C  += (size_t)blockIdx.z * sC;

    __shared__ float As[8][128];
    __shared__ float Bs[8][128];

    const int tid  = threadIdx.x;
    const int brow = blockIdx.y * 128;
    const int bcol = blockIdx.x * 128;

    const int lr = tid >> 1;           // 0..127  (A / NT-B tile row)
    const int lc = (tid & 1) * 4;      // 0 or 4  (k offset)
    const int nr = tid >> 5;           // 0..7    (NN-B tile k row)
    const int nc = (tid & 31) * 4;     // 0..124  (NN-B tile col)

    const int ty = tid >> 4;           // 0..15
    const int tx = tid & 15;           // 0..15

    float acc[8][8];
#pragma unroll
    for (int i = 0; i < 8; i++)
#pragma unroll
        for (int j = 0; j < 8; j++) acc[i][j] = 0.0f;

    for (int k0 = 0; k0 < K; k0 += 8) {
        // load A tile (transposed into As[k][m])
        float4 av = *reinterpret_cast<const float4*>(
            &A[(size_t)(brow + lr) * K + k0 + lc]);
        As[lc + 0][lr] = av.x;
        As[lc + 1][lr] = av.y;
        As[lc + 2][lr] = av.z;
        As[lc + 3][lr] = av.w;

        if (TRANSB) {
            float4 bv4 = *reinterpret_cast<const float4*>(
                &Bm[(size_t)(bcol + lr) * K + k0 + lc]);
            Bs[lc + 0][lr] = bv4.x;
            Bs[lc + 1][lr] = bv4.y;
            Bs[lc + 2][lr] = bv4.z;
            Bs[lc + 3][lr] = bv4.w;
        } else {
            *reinterpret_cast<float4*>(&Bs[nr][nc]) =
                *reinterpret_cast<const float4*>(
                    &Bm[(size_t)(k0 + nr) * N + bcol + nc]);
        }
        __syncthreads();

#pragma unroll
        for (int k = 0; k < 8; k++) {
            float4 a0 = *reinterpret_cast<const float4*>(&As[k][ty * 4]);
            float4 a1 = *reinterpret_cast<const float4*>(&As[k][64 + ty * 4]);
            float4 b0 = *reinterpret_cast<const float4*>(&Bs[k][tx * 4]);
            float4 b1 = *reinterpret_cast<const float4*>(&Bs[k][64 + tx * 4]);
            float a[8] = {a0.x, a0.y, a0.z, a0.w, a1.x, a1.y, a1.z, a1.w};
            float b[8] = {b0.x, b0.y, b0.z, b0.w, b1.x, b1.y, b1.z, b1.w};
#pragma unroll
            for (int i = 0; i < 8; i++)
#pragma unroll
                for (int j = 0; j < 8; j++)
                    acc[i][j] = fmaf(a[i], b[j], acc[i][j]);
        }
        __syncthreads();
    }

    // epilogue: rows {brow + ih*64 + ty*4 + ii}, cols {bcol + jh*64 + tx*4 + jj}
#pragma unroll
    for (int ih = 0; ih < 2; ih++) {
#pragma unroll
        for (int ii = 0; ii < 4; ii++) {
            const int i = ih * 4 + ii;
            const int r = brow + ih * 64 + ty * 4 + ii;
#pragma unroll
            for (int jh = 0; jh < 2; jh++) {
                const int c0 = bcol + jh * 64 + tx * 4;
                float4 o;
                float* op = reinterpret_cast<float*>(&o);
#pragma unroll
                for (int jj = 0; jj < 4; jj++) {
                    const int j = jh * 4 + jj;
                    const int c = c0 + jj;
                    float val = acc[i][j];
                    if (MODE == 0) {
                        val += bias[c];
                    } else if (MODE == 1) {
                        // multiplicative tril mask: masked-out -> exp(0) = 1
                        val = (r >= c) ? __expf(val * ATTN_SCALE) * 0.0f + expf(val * ATTN_SCALE)
                                       : 1.0f;
                        // (use accurate expf; line above keeps expf only)
                        val = (r >= c) ? expf(acc[i][j] * ATTN_SCALE) : 1.0f;
                    }
                    op[jj] = val;
                }
                *reinterpret_cast<float4*>(&C[(size_t)r * N + c0]) = o;
            }
        }
    }
}

// column sums over query axis (softmax axis=1), store reciprocal
__global__ __launch_bounds__(256) void colsum_inv(
    const float* __restrict__ E, float* __restrict__ Dinv)
{
    const int b = blockIdx.y;
    const int k = blockIdx.x * 256 + threadIdx.x;
    const float* Eb = E + (size_t)b * Tn * Tn;
    float s0 = 0.f, s1 = 0.f, s2 = 0.f, s3 = 0.f;
    for (int q = 0; q < Tn; q += 4) {
        s0 += Eb[(size_t)(q + 0) * Tn + k];
        s1 += Eb[(size_t)(q + 1) * Tn + k];
        s2 += Eb[(size_t)(q + 2) * Tn + k];
        s3 += Eb[(size_t)(q + 3) * Tn + k];
    }
    Dinv[b * Tn + k] = 1.0f / ((s0 + s1) + (s2 + s3));
}

// v'[b,k,h] = v[b,k,h] * Dinv[b,k]   (H = 2048 -> 512 float4 per row)
__global__ __launch_bounds__(256) void vscale(
    float* __restrict__ V, const float* __restrict__ Dinv)
{
    const size_t i4 = (size_t)blockIdx.x * 256 + threadIdx.x;
    float4 v4 = reinterpret_cast<float4*>(V)[i4];
    const float s = Dinv[i4 >> 9];
    v4.x *= s; v4.y *= s; v4.z *= s; v4.w *= s;
    reinterpret_cast<float4*>(V)[i4] = v4;
}

extern "C" void kernel_launch(void* const* d_in, const int* in_sizes, int n_in,
                              void* d_out, int out_size)
{
    (void)in_sizes; (void)n_in; (void)out_size;
    const float* x  = (const float*)d_in[0];
    const float* Wq = (const float*)d_in[1];
    const float* bq = (const float*)d_in[2];
    const float* Wv = (const float*)d_in[3];
    const float* bv = (const float*)d_in[4];
    float* out = (float*)d_out;

    float *q, *v, *e, *dI;
    cudaGetSymbolAddress((void**)&q,  g_q);
    cudaGetSymbolAddress((void**)&v,  g_v);
    cudaGetSymbolAddress((void**)&e,  g_e);
    cudaGetSymbolAddress((void**)&dI, g_d);

    const dim3 blk(256);
    const size_t sQV = (size_t)Tn * Hn;   // per-batch stride of q/v
    const size_t sE  = (size_t)Tn * Tn;   // per-batch stride of E / out

    // projections: [B*T, E] @ [E, H] + bias
    gemm128<false, 0><<<dim3(Hn / 128, (Bn * Tn) / 128, 1), blk>>>(
        x, Wq, bq, q, Bn * Tn, Hn, En, 0, 0, 0);
    gemm128<false, 0><<<dim3(Hn / 128, (Bn * Tn) / 128, 1), blk>>>(
        x, Wv, bv, v, Bn * Tn, Hn, En, 0, 0, 0);

    // E = exp(mask .* (q @ q^T) * scale), per batch (NT)
    gemm128<true, 1><<<dim3(Tn / 128, Tn / 128, Bn), blk>>>(
        q, q, nullptr, e, Tn, Tn, Hn, sQV, sQV, sE);

    // softmax denominators over query axis -> reciprocals
    colsum_inv<<<dim3(Tn / 256, Bn), blk>>>(e, dI);

    // fold 1/D into v rows
    vscale<<<dim3((Bn * Tn * Hn) / (4 * 256)), blk>>>(v, dI);

    // out = E @ v'
    gemm128<false, 2><<<dim3(Hn / 128, Tn / 128, Bn), blk>>>(
        e, v, nullptr, out, Tn, Hn, Tn, sE, sQV, sQV);
}

// round 3
// speedup vs baseline: 3.0563x; 3.0563x over previous
#include <cuda_runtime.h>
#include <math.h>
#include <stdint.h>

#define Bn 4
#define Tn 2048
#define En 1024
#define Hn 2048
#define BT (Bn*Tn)
#define ATTN_SCALE 0.022097086912079612f

// ---------------- scratch (static device memory; no cudaMalloc) -------------
__device__ float g_q  [(size_t)BT * Hn];   // q (tf32-rounded)
__device__ float g_vt [(size_t)Hn * BT];   // v^T as [H, B*T]
__device__ float g_e  [(size_t)BT * Tn];   // exp'd masked scores
__device__ float g_xr [(size_t)BT * En];   // x rounded to tf32
__device__ float g_wtq[(size_t)Hn * En];   // Wq^T rounded
__device__ float g_wtv[(size_t)Hn * En];   // Wv^T rounded
__device__ float g_d  [BT];                // softmax denominators

// ---------------- helpers ----------------------------------------------------
__device__ __forceinline__ float tf32r(float x) {
    uint32_t u;
    asm("cvt.rna.tf32.f32 %0, %1;" : "=r"(u) : "f"(x));
    return __uint_as_float(u);
}
__device__ __forceinline__ uint32_t smem_u32(const void* p) {
    uint32_t a;
    asm("{ .reg .u64 t; cvta.to.shared.u64 t, %1; cvt.u32.u64 %0, t; }" : "=r"(a) : "l"(p));
    return a;
}
__device__ __forceinline__ void cp16(uint32_t s, const void* g) {
    asm volatile("cp.async.ca.shared.global [%0], [%1], 16;" :: "r"(s), "l"(g));
}
#define CP_COMMIT() asm volatile("cp.async.commit_group;" ::: "memory")
#define CP_WAIT(n)  asm volatile("cp.async.wait_group %0;" :: "n"(n) : "memory")

__device__ __forceinline__ void mma8(float* d, const uint32_t* a, const uint32_t* b) {
    asm volatile(
        "mma.sync.aligned.m16n8k8.row.col.f32.tf32.tf32.f32 "
        "{%0,%1,%2,%3}, {%4,%5,%6,%7}, {%8,%9}, {%0,%1,%2,%3};"
        : "+f"(d[0]), "+f"(d[1]), "+f"(d[2]), "+f"(d[3])
        : "r"(a[0]), "r"(a[1]), "r"(a[2]), "r"(a[3]), "r"(b[0]), "r"(b[1]));
}

// ---------------- tensor-core GEMM (NT: A[M,K] x B[N,K] -> C[M,N]) -----------
// MODE 0: C = tf32(acc + bias[col])      (q projection)
// MODE 1: C = tf32(acc + bias[row])      (v^T projection)
// MODE 2: C = tf32(r>=c ? exp(acc*s):1)  (scores -> E)
// MODE 3: C = acc                        (final output)
#define LDS_S 36                    // padded smem row stride (floats)
#define STAGE_F (128 * LDS_S)       // 4608 floats per tile stage
#define SMEM_BYTES (4 * STAGE_F * 4)  // A0,A1,B0,B1 = 73728 B

template <int MODE>
__global__ void __launch_bounds__(256, 2) mm_mma(
    const float* __restrict__ A, const float* __restrict__ B,
    const float* __restrict__ bias, float* __restrict__ C,
    int K, int ldA, int ldB, int ldC,
    long long zA, long long zB, long long zC)
{
    extern __shared__ float sm[];
    const int z = blockIdx.z;
    A += z * zA; B += z * zB; C += z * zC;

    const int tid  = threadIdx.x;
    const int wid  = tid >> 5, lane = tid & 31;
    const int wm   = wid & 1, wn = wid >> 1;      // warp tile: 64x32
    const int grp  = lane >> 2, tig = lane & 3;
    const int brow = blockIdx.y * 128, bcol = blockIdx.x * 128;

    float* As[2] = { sm,             sm + STAGE_F };
    float* Bs[2] = { sm + 2*STAGE_F, sm + 3*STAGE_F };
    const uint32_t sA0 = smem_u32(As[0]), sB0 = smem_u32(Bs[0]);

    // tile loaders: 128 rows x 32 cols, 1024 float4, 256 threads x 4
    const int lr = tid >> 3, lc4 = (tid & 7) * 4;       // row, col within tile

    float acc[4][4][4];
#pragma unroll
    for (int i = 0; i < 4; i++)
#pragma unroll
        for (int j = 0; j < 4; j++)
#pragma unroll
            for (int k = 0; k < 4; k++) acc[i][j][k] = 0.0f;

    const int nk = K >> 5;

    // prologue: stage 0
#pragma unroll
    for (int j = 0; j < 4; j++) {
        const int r = lr + 32 * j;
        cp16(sA0 + (r * LDS_S + lc4) * 4, A + (size_t)(brow + r) * ldA + lc4);
        cp16(sB0 + (r * LDS_S + lc4) * 4, B + (size_t)(bcol + r) * ldB + lc4);
    }
    CP_COMMIT();

    for (int i = 0; i < nk; i++) {
        const int cur = i & 1;
        if (i + 1 < nk) {
            const int nxt = cur ^ 1;
            const int k0 = (i + 1) * 32;
            const uint32_t sAn = sA0 + nxt * STAGE_F * 4;
            const uint32_t sBn = sB0 + (nxt + 2) * STAGE_F * 4 - 2 * STAGE_F * 4; // = sB0 + nxt*STAGE_F*4
#pragma unroll
            for (int j = 0; j < 4; j++) {
                const int r = lr + 32 * j;
                cp16(sAn + (r * LDS_S + lc4) * 4, A + (size_t)(brow + r) * ldA + k0 + lc4);
                cp16(sBn + (r * LDS_S + lc4) * 4, B + (size_t)(bcol + r) * ldB + k0 + lc4);
            }
            CP_COMMIT();
            CP_WAIT(1);
        } else {
            CP_WAIT(0);
        }
        __syncthreads();

        const float* as = As[cur];
        const float* bs = Bs[cur];
#pragma unroll
        for (int k8 = 0; k8 < 4; k8++) {
            uint32_t afr[4][4], bfr[4][2];
#pragma unroll
            for (int mi = 0; mi < 4; mi++) {
                const float* p = as + (wm * 64 + mi * 16 + grp) * LDS_S + k8 * 8 + tig;
                afr[mi][0] = __float_as_uint(p[0]);
                afr[mi][1] = __float_as_uint(p[8 * LDS_S]);
                afr[mi][2] = __float_as_uint(p[4]);
                afr[mi][3] = __float_as_uint(p[8 * LDS_S + 4]);
            }
#pragma unroll
            for (int ni = 0; ni < 4; ni++) {
                const float* p = bs + (wn * 32 + ni * 8 + grp) * LDS_S + k8 * 8 + tig;
                bfr[ni][0] = __float_as_uint(p[0]);
                bfr[ni][1] = __float_as_uint(p[4]);
            }
#pragma unroll
            for (int mi = 0; mi < 4; mi++)
#pragma unroll
                for (int ni = 0; ni < 4; ni++)
                    mma8(acc[mi][ni], afr[mi], bfr[ni]);
        }
        __syncthreads();
    }

    // ---------------- epilogue ----------------
#pragma unroll
    for (int mi = 0; mi < 4; mi++) {
        const int r0 = brow + wm * 64 + mi * 16 + grp;   // batch-local row
#pragma unroll
        for (int half = 0; half < 2; half++) {
            const int r = r0 + half * 8;
            float rbias = 0.0f;
            if (MODE == 1) rbias = __ldg(&bias[r]);
#pragma unroll
            for (int ni = 0; ni < 4; ni++) {
                const int c = bcol + wn * 32 + ni * 8 + 2 * tig;
                float v0 = acc[mi][ni][half * 2 + 0];
                float v1 = acc[mi][ni][half * 2 + 1];
                if (MODE == 0) {
                    v0 = tf32r(v0 + __ldg(&bias[c]));
                    v1 = tf32r(v1 + __ldg(&bias[c + 1]));
                } else if (MODE == 1) {
                    v0 = tf32r(v0 + rbias);
                    v1 = tf32r(v1 + rbias);
                } else if (MODE == 2) {
                    v0 = tf32r((r >= c)     ? expf(v0 * ATTN_SCALE) : 1.0f);
                    v1 = tf32r((r >= c + 1) ? expf(v1 * ATTN_SCALE) : 1.0f);
                }
                *reinterpret_cast<float2*>(C + (size_t)r * ldC + c) = make_float2(v0, v1);
            }
        }
    }
}

// ---------------- small kernels ---------------------------------------------
__global__ void __launch_bounds__(256) transpose_round(
    const float* __restrict__ src, float* __restrict__ dst, int R, int Cc)
{
    __shared__ float t[32][33];
    const int x = blockIdx.x * 32 + threadIdx.x;
    const int y0 = blockIdx.y * 32;
#pragma unroll
    for (int j = 0; j < 32; j += 8)
        t[threadIdx.y + j][threadIdx.x] = src[(size_t)(y0 + threadIdx.y + j) * Cc + x];
    __syncthreads();
    const int xo = y0 + threadIdx.x;
    const int yo0 = blockIdx.x * 32;
#pragma unroll
    for (int j = 0; j < 32; j += 8)
        dst[(size_t)(yo0 + threadIdx.y + j) * R + xo] = tf32r(t[threadIdx.x][threadIdx.y + j]);
}

__global__ void __launch_bounds__(256) round_x(const float* __restrict__ in, float* __restrict__ o)
{
    const size_t i = (size_t)blockIdx.x * 256 + threadIdx.x;
    float4 v = reinterpret_cast<const float4*>(in)[i];
    v.x = tf32r(v.x); v.y = tf32r(v.y); v.z = tf32r(v.z); v.w = tf32r(v.w);
    reinterpret_cast<float4*>(o)[i] = v;
}

__global__ void __launch_bounds__(256) zero_d(float* __restrict__ D)
{
    D[blockIdx.x * 256 + threadIdx.x] = 0.0f;
}

// D[b*Tn + k] += sum over a 256-row chunk of E[:, k] (softmax over query axis)
__global__ void __launch_bounds__(256) colsum(const float* __restrict__ E, float* __restrict__ D)
{
    const int k = blockIdx.x * 256 + threadIdx.x;
    const int b = blockIdx.y;
    const int rc = blockIdx.z;
    const float* p = E + ((size_t)b * Tn + (size_t)rc * 256) * Tn + k;
    float s = 0.0f;
#pragma unroll 8
    for (int q = 0; q < 256; q++) s += p[(size_t)q * Tn];
    atomicAdd(&D[b * Tn + k], s);
}

// vt[h, b*T+t] /= D[b*T+t], round to tf32
__global__ void __launch_bounds__(256) vtscale(float* __restrict__ VT, const float* __restrict__ D)
{
    const size_t i4 = (size_t)blockIdx.x * 256 + threadIdx.x;
    float4 v = reinterpret_cast<float4*>(VT)[i4];
    const int col4 = (int)(i4 & (BT / 4 - 1));
    const float4 d = reinterpret_cast<const float4*>(D)[col4];
    v.x = tf32r(v.x / d.x); v.y = tf32r(v.y / d.y);
    v.z = tf32r(v.z / d.z); v.w = tf32r(v.w / d.w);
    reinterpret_cast<float4*>(VT)[i4] = v;
}

// ---------------- host -------------------------------------------------------
extern "C" void kernel_launch(void* const* d_in, const int* in_sizes, int n_in,
                              void* d_out, int out_size)
{
    (void)in_sizes; (void)n_in; (void)out_size;
    const float* x  = (const float*)d_in[0];
    const float* Wq = (const float*)d_in[1];
    const float* bq = (const float*)d_in[2];
    const float* Wv = (const float*)d_in[3];
    const float* bv = (const float*)d_in[4];
    float* out = (float*)d_out;

    float *q, *vt, *e, *xr, *wtq, *wtv, *dI;
    cudaGetSymbolAddress((void**)&q,   g_q);
    cudaGetSymbolAddress((void**)&vt,  g_vt);
    cudaGetSymbolAddress((void**)&e,   g_e);
    cudaGetSymbolAddress((void**)&xr,  g_xr);
    cudaGetSymbolAddress((void**)&wtq, g_wtq);
    cudaGetSymbolAddress((void**)&wtv, g_wtv);
    cudaGetSymbolAddress((void**)&dI,  g_d);

    cudaFuncSetAttribute(mm_mma<0>, cudaFuncAttributeMaxDynamicSharedMemorySize, SMEM_BYTES);
    cudaFuncSetAttribute(mm_mma<1>, cudaFuncAttributeMaxDynamicSharedMemorySize, SMEM_BYTES);
    cudaFuncSetAttribute(mm_mma<2>, cudaFuncAttributeMaxDynamicSharedMemorySize, SMEM_BYTES);
    cudaFuncSetAttribute(mm_mma<3>, cudaFuncAttributeMaxDynamicSharedMemorySize, SMEM_BYTES);

    // prep: transpose+round weights, round x, zero denominators
    transpose_round<<<dim3(Hn / 32, En / 32), dim3(32, 8)>>>(Wq, wtq, En, Hn);
    transpose_round<<<dim3(Hn / 32, En / 32), dim3(32, 8)>>>(Wv, wtv, En, Hn);
    round_x<<<(int)(((size_t)BT * En / 4) / 256), 256>>>(x, xr);
    zero_d<<<BT / 256, 256>>>(dI);

    // q = x @ Wq + bq                    [B*T, H]
    mm_mma<0><<<dim3(Hn / 128, BT / 128, 1), 256, SMEM_BYTES>>>(
        xr, wtq, bq, q, En, En, En, Hn, 0, 0, 0);
    // v^T = (x @ Wv + bv)^T              [H, B*T]
    mm_mma<1><<<dim3(BT / 128, Hn / 128, 1), 256, SMEM_BYTES>>>(
        wtv, xr, bv, vt, En, En, En, BT, 0, 0, 0);
    // E = exp(mask .* (q @ q^T) * s)     per batch
    mm_mma<2><<<dim3(Tn / 128, Tn / 128, Bn), 256, SMEM_BYTES>>>(
        q, q, nullptr, e, Hn, Hn, Hn, Tn,
        (long long)Tn * Hn, (long long)Tn * Hn, (long long)Tn * Tn);
    // softmax denominators + fold into v^T columns
    colsum<<<dim3(Tn / 256, Bn, Tn / 256), 256>>>(e, dI);
    vtscale<<<(int)(((size_t)Hn * BT / 4) / 256), 256>>>(vt, dI);
    // out = E @ v'                       per batch
    mm_mma<3><<<dim3(Hn / 128, Tn / 128, Bn), 256, SMEM_BYTES>>>(
        e, vt, nullptr, out, Tn, Tn, BT, Hn,
        (long long)Tn * Tn, (long long)Tn, (long long)Tn * Hn);
}